// round 3
// baseline (speedup 1.0000x reference)
#include <cuda_runtime.h>

// out = noised + 0.1f * noise   (elementwise, N = 50,331,648 fp32)
// Blackwell 256-bit global ld/st (v8.f32) streaming kernel.
// Each thread: 2x 256-bit loads + 1x 256-bit store = 8 elements.

__device__ __forceinline__ void ld_256_cs(const float* __restrict__ p, float r[8]) {
    asm volatile(
        "ld.global.cs.v8.f32 {%0,%1,%2,%3,%4,%5,%6,%7}, [%8];"
        : "=f"(r[0]), "=f"(r[1]), "=f"(r[2]), "=f"(r[3]),
          "=f"(r[4]), "=f"(r[5]), "=f"(r[6]), "=f"(r[7])
        : "l"(p));
}

__device__ __forceinline__ void st_256_cs(float* __restrict__ p, const float r[8]) {
    asm volatile(
        "st.global.cs.v8.f32 [%0], {%1,%2,%3,%4,%5,%6,%7,%8};"
        :
        : "l"(p),
          "f"(r[0]), "f"(r[1]), "f"(r[2]), "f"(r[3]),
          "f"(r[4]), "f"(r[5]), "f"(r[6]), "f"(r[7])
        : "memory");
}

__global__ void __launch_bounds__(256) gaussian_noise_axpy_v8(
    const float* __restrict__ noised,
    const float* __restrict__ noise,
    float* __restrict__ out,
    int n8)   // number of 8-element groups
{
    int i = blockIdx.x * blockDim.x + threadIdx.x;
    if (i < n8) {
        const float* pa = noised + (size_t)i * 8;
        const float* pb = noise  + (size_t)i * 8;
        float*       po = out    + (size_t)i * 8;

        float a[8], b[8], r[8];
        ld_256_cs(pa, a);
        ld_256_cs(pb, b);
        #pragma unroll
        for (int k = 0; k < 8; k++)
            r[k] = fmaf(0.1f, b[k], a[k]);
        st_256_cs(po, r);
    }
}

// Scalar tail (n not divisible by 8; not expected for this shape).
__global__ void gaussian_noise_axpy_tail(
    const float* __restrict__ noised,
    const float* __restrict__ noise,
    float* __restrict__ out,
    int start, int n)
{
    int i = start + blockIdx.x * blockDim.x + threadIdx.x;
    if (i < n) {
        out[i] = fmaf(0.1f, noise[i], noised[i]);
    }
}

extern "C" void kernel_launch(void* const* d_in, const int* in_sizes, int n_in,
                              void* d_out, int out_size)
{
    const float* noised = (const float*)d_in[0];
    const float* noise  = (const float*)d_in[1];
    float* out = (float*)d_out;
    int n = in_sizes[0];

    int n8 = n >> 3;   // 8 elements per thread via 256-bit accesses
    if (n8 > 0) {
        const int threads = 256;
        int blocks = (n8 + threads - 1) / threads;
        gaussian_noise_axpy_v8<<<blocks, threads>>>(noised, noise, out, n8);
    }
    int done = n8 << 3;
    if (done < n) {
        int rem = n - done;
        gaussian_noise_axpy_tail<<<(rem + 255) / 256, 256>>>(noised, noise, out, done, n);
    }
}